// round 6
// baseline (speedup 1.0000x reference)
#include <cuda_runtime.h>
#include <cuda_bf16.h>
#include <mma.h>
#include <cstdint>

using namespace nvcuda;

#define B_    16
#define S_    16
#define D_    4096
#define H_    32
#define KV_   8
#define HD_   128
#define T_    256
#define KVLEN 4096
#define STARTP 4080
#define NQKV  6144

// ----------------------------- device scratch ------------------------------
__device__ float g_qkv[T_ * NQKV];
__device__ float g_attn[T_ * D_];

// ----------------------------- helpers ---------------------------------
__device__ __forceinline__ uint32_t smem_u32(const void* p) {
    uint32_t a;
    asm("{ .reg .u64 t; cvta.to.shared.u64 t, %1; cvt.u32.u64 %0, t; }" : "=r"(a) : "l"(p));
    return a;
}
__device__ __forceinline__ void cp16(uint32_t dst, const void* src) {
    asm volatile("cp.async.cg.shared.global [%0], [%1], 16;" :: "r"(dst), "l"(src));
}
__device__ __forceinline__ void cp_commit() { asm volatile("cp.async.commit_group;" ::: "memory"); }
template<int N> __device__ __forceinline__ void cp_wait() {
    asm volatile("cp.async.wait_group %0;" :: "n"(N) : "memory");
}
__device__ __forceinline__ float to_tf32(float x) { return wmma::__float_to_tf32(x); }

template<class Frag>
__device__ __forceinline__ void round_frag(Frag& f) {
#pragma unroll
    for (int i = 0; i < f.num_elements; i++) f.x[i] = to_tf32(f.x[i]);
}

// ---------------------------------------------------------------------------
// tf32 GEMM, 512 threads (16 warps, 4x4 grid, 32x32 warp tiles), BK=64,
// 2-stage cp.async. Reads RAW fp32 operands; fragments RN-rounded in regs.
// qkv_mode=1: B/bias selected per N-tile from wq|wk|wv / bq|bk|bv.
// ---------------------------------------------------------------------------
#define GBK 64
#define GLDA 68
#define GLDB 132
#define G_A_FLOATS (128 * GLDA)
#define G_STAGE_FLOATS (G_A_FLOATS + GBK * GLDB)   // 8704+8448=17152
#define G_SMEM (2 * G_STAGE_FLOATS * 4)            // 137216

__global__ __launch_bounds__(512) void gemm_fused(
    const float* __restrict__ A,
    const float* __restrict__ w0, const float* __restrict__ w1, const float* __restrict__ w2,
    const float* __restrict__ b0, const float* __restrict__ b1, const float* __restrict__ b2,
    float* __restrict__ C, int Nt, int K, int qkv_mode)
{
    extern __shared__ __align__(16) float sm[];
    float* stage[2] = { sm, sm + G_STAGE_FLOATS };

    const int tid  = threadIdx.x;
    const int warp = tid >> 5;
    const int wm   = warp >> 2;       // 0..3 -> rows wm*32
    const int wn   = warp & 3;        // 0..3 -> cols wn*32
    const int m0 = blockIdx.y * 128;
    const int n0 = blockIdx.x * 128;
    const int NC = K / GBK;

    // B source / bias selection (tile fully inside one region: 128 | 4096,1024)
    const float* Bsrc; const float* biasp; int bstride;
    if (qkv_mode) {
        if (n0 < 4096)      { Bsrc = w0; biasp = b0 + n0;        bstride = 4096; }
        else if (n0 < 5120) { Bsrc = w1; biasp = b1 + (n0-4096); bstride = 1024; }
        else                { Bsrc = w2; biasp = b2 + (n0-5120); bstride = 1024; }
        Bsrc += (n0 < 4096) ? n0 : (n0 < 5120 ? n0 - 4096 : n0 - 5120);
    } else {
        Bsrc = w0 + n0; biasp = b0 + n0; bstride = Nt;
    }

    const uint32_t sa[2] = { smem_u32(stage[0]), smem_u32(stage[1]) };

    auto load_tile = [&](int c, int b) {
        const int k0 = c * GBK;
        const uint32_t st = sa[b];
        const uint32_t stB = st + G_A_FLOATS * 4;
#pragma unroll
        for (int i = tid; i < 2048; i += 512) {          // A: 128 x 16 float4
            int r = i >> 4, c4 = (i & 15) << 2;
            cp16(st + (uint32_t)(r * GLDA + c4) * 4u, A + (size_t)(m0 + r) * K + k0 + c4);
        }
#pragma unroll
        for (int i = tid; i < 2048; i += 512) {          // B: 64 x 32 float4
            int r = i >> 5, c4 = (i & 31) << 2;
            cp16(stB + (uint32_t)(r * GLDB + c4) * 4u, Bsrc + (size_t)(k0 + r) * bstride + c4);
        }
        cp_commit();
    };

    wmma::fragment<wmma::accumulator, 16, 16, 8, float> acc[2][2];
#pragma unroll
    for (int i = 0; i < 2; i++)
#pragma unroll
        for (int j = 0; j < 2; j++) wmma::fill_fragment(acc[i][j], 0.0f);

    load_tile(0, 0);
    load_tile(1, 1);

    for (int c = 0; c < NC; c++) {
        const int b = c & 1;
        if (c + 1 < NC) cp_wait<1>(); else cp_wait<0>();
        __syncthreads();

        const float* As = stage[b];
        const float* Bs = stage[b] + G_A_FLOATS;
#pragma unroll
        for (int kk = 0; kk < GBK; kk += 8) {
            wmma::fragment<wmma::matrix_a, 16, 16, 8, wmma::precision::tf32, wmma::row_major> a[2];
            wmma::fragment<wmma::matrix_b, 16, 16, 8, wmma::precision::tf32, wmma::row_major> bf[2];
#pragma unroll
            for (int i = 0; i < 2; i++) {
                wmma::load_matrix_sync(a[i], As + (wm * 32 + i * 16) * GLDA + kk, GLDA);
                round_frag(a[i]);
            }
#pragma unroll
            for (int j = 0; j < 2; j++) {
                wmma::load_matrix_sync(bf[j], Bs + kk * GLDB + wn * 32 + j * 16, GLDB);
                round_frag(bf[j]);
            }
#pragma unroll
            for (int i = 0; i < 2; i++)
#pragma unroll
                for (int j = 0; j < 2; j++)
                    wmma::mma_sync(acc[i][j], a[i], bf[j], acc[i][j]);
        }
        __syncthreads();
        if (c + 2 < NC) load_tile(c + 2, b);
    }

    // epilogue
    float* Cs = sm;
#pragma unroll
    for (int i = 0; i < 2; i++)
#pragma unroll
        for (int j = 0; j < 2; j++)
            wmma::store_matrix_sync(Cs + (wm * 32 + i * 16) * GLDB + wn * 32 + j * 16,
                                    acc[i][j], GLDB, wmma::mem_row_major);
    __syncthreads();
    for (int i = tid; i < 128 * 32; i += 512) {
        int r = i >> 5, c4 = (i & 31) << 2;
        float4 v = *reinterpret_cast<float4*>(Cs + r * GLDB + c4);
        float4 bb = *reinterpret_cast<const float4*>(biasp + c4);
        v.x += bb.x; v.y += bb.y; v.z += bb.z; v.w += bb.w;
        *reinterpret_cast<float4*>(C + (size_t)(m0 + r) * Nt + n0 + c4) = v;
    }
}

// ---------------------------------------------------------------------------
// RoPE in place on g_qkv
// ---------------------------------------------------------------------------
__global__ void rope_kernel(const float* __restrict__ fc, const float* __restrict__ fs)
{
    const int QP = T_ * H_ * 64;
    const int KP = T_ * KV_ * 64;
    int idx = blockIdx.x * blockDim.x + threadIdx.x;
    if (idx < QP) {
        int c = idx & 63, h = (idx >> 6) & 31, m = idx >> 11;
        int s = m & 15;
        float co = fc[s * 64 + c], sn = fs[s * 64 + c];
        float* p = g_qkv + (size_t)m * NQKV + h * 128 + 2 * c;
        float x0 = p[0], x1 = p[1];
        p[0] = x0 * co - x1 * sn;
        p[1] = x0 * sn + x1 * co;
    } else if (idx < QP + KP) {
        int j = idx - QP;
        int c = j & 63, kvh = (j >> 6) & 7, m = j >> 9;
        int s = m & 15;
        float co = fc[s * 64 + c], sn = fs[s * 64 + c];
        float* p = g_qkv + (size_t)m * NQKV + 4096 + kvh * 128 + 2 * c;
        float x0 = p[0], x1 = p[1];
        p[0] = x0 * co - x1 * sn;
        p[1] = x0 * sn + x1 * co;
    }
}

// ---------------------------------------------------------------------------
// attention: 512 threads / 16 warps. K rounded in-fragment (no convert phase).
// 4x4 warp grid: QK -> 16x16 S tiles; PV -> 16x32 O tiles.
// ---------------------------------------------------------------------------
#define LDQ 132
#define LDS 68
#define ATT_SMEM ((64 * LDQ * 5 + 64 * LDS + 64) * 4)

__global__ __launch_bounds__(512) void attn_kernel(
    const float* __restrict__ cache_k, const float* __restrict__ cache_v)
{
    extern __shared__ __align__(16) float smem[];
    float* Qs   = smem;
    float* Kb0  = Qs + 64 * LDQ;
    float* Kb1  = Kb0 + 64 * LDQ;
    float* Vb0  = Kb1 + 64 * LDQ;
    float* Vb1  = Vb0 + 64 * LDQ;
    float* Ss   = Vb1 + 64 * LDQ;
    float* lrow = Ss + 64 * LDS;

    const int b   = blockIdx.x >> 3;
    const int kvh = blockIdx.x & 7;
    const int tid = threadIdx.x;
    const int warp = tid >> 5;
    const int wm = warp >> 2;      // 0..3 : 16-row group
    const int wn = warp & 3;       // 0..3

    const uint32_t kaddr[2] = { smem_u32(Kb0), smem_u32(Kb1) };
    const uint32_t vaddr[2] = { smem_u32(Vb0), smem_u32(Vb1) };

    auto load_tile = [&](int t, int bb) {
        const int p0 = t * 64;
        const uint32_t ka = kaddr[bb], va = vaddr[bb];
#pragma unroll
        for (int i = tid; i < 2048; i += 512) {
            int r = i >> 5, c16 = i & 31;
            int p = p0 + r;
            const float *srck, *srcv;
            if (p < STARTP) {
                size_t o = (((size_t)b * KVLEN + p) * KV_ + kvh) * (size_t)HD_ + c16 * 4;
                srck = cache_k + o; srcv = cache_v + o;
            } else {
                size_t row = (size_t)(b * 16 + p - STARTP) * NQKV;
                srck = g_qkv + row + 4096 + kvh * 128 + c16 * 4;
                srcv = g_qkv + row + 5120 + kvh * 128 + c16 * 4;
            }
            uint32_t doff = (uint32_t)(r * LDQ + c16 * 4) * 4u;
            cp16(ka + doff, srck);
            cp16(va + doff, srcv);
        }
        cp_commit();
    };

    load_tile(0, 0);
    load_tile(1, 1);

    const float scale = 0.08838834764831845f;
    for (int i = tid; i < 64 * 32; i += 512) {
        int j = i >> 5, c = (i & 31) << 2;
        int s = j & 15, hr = j >> 4;
        float4 v = *reinterpret_cast<const float4*>(
            g_qkv + (size_t)(b * 16 + s) * NQKV + (kvh * 4 + hr) * HD_ + c);
        float* d = Qs + j * LDQ + c;
        d[0] = to_tf32(v.x * scale); d[1] = to_tf32(v.y * scale);
        d[2] = to_tf32(v.z * scale); d[3] = to_tf32(v.w * scale);
    }
    if (tid < 64) lrow[tid] = 0.0f;
    __syncthreads();

    // hoist Q fragments (16 k-steps for this warp's 16-row block)
    wmma::fragment<wmma::matrix_a, 16, 16, 8, wmma::precision::tf32, wmma::row_major> qf[16];
#pragma unroll
    for (int kk = 0; kk < 16; kk++)
        wmma::load_matrix_sync(qf[kk], Qs + (wm * 16) * LDQ + kk * 8, LDQ);

    wmma::fragment<wmma::accumulator, 16, 16, 8, float> o_acc[2];
#pragma unroll
    for (int j = 0; j < 2; j++) wmma::fill_fragment(o_acc[j], 0.0f);

    for (int t = 0; t < KVLEN / 64; t++) {
        const int bb = t & 1;
        float* Kc = bb ? Kb1 : Kb0;
        float* Vc = bb ? Vb1 : Vb0;
        const int p0 = t * 64;

        if (t + 1 < KVLEN / 64) cp_wait<1>(); else cp_wait<0>();
        __syncthreads();

        // S = Q K^T : warp tile 16x16, K rounded in-fragment
        {
            wmma::fragment<wmma::accumulator, 16, 16, 8, float> s_acc;
            wmma::fill_fragment(s_acc, 0.0f);
#pragma unroll
            for (int kk = 0; kk < 16; kk++) {
                wmma::fragment<wmma::matrix_b, 16, 16, 8, wmma::precision::tf32, wmma::col_major> bk;
                wmma::load_matrix_sync(bk, Kc + (wn * 16) * LDQ + kk * 8, LDQ);
                round_frag(bk);
                wmma::mma_sync(s_acc, qf[kk], bk, s_acc);
            }
            wmma::store_matrix_sync(Ss + (wm * 16) * LDS + wn * 16, s_acc, LDS,
                                    wmma::mem_row_major);
        }
        __syncthreads();

        // exp + causal mask + row sums (512 threads: 8 cols each)
        {
            int r = tid >> 3, part = tid & 7;
            int lim = STARTP + (r & 15);
            float* row = Ss + r * LDS + part * 8;
            int pbase = p0 + part * 8;
            float sum = 0.0f;
#pragma unroll
            for (int c = 0; c < 8; c++) {
                float v = row[c];
                float pv = (pbase + c <= lim) ? __expf(v) : 0.0f;
                sum += pv;
                row[c] = to_tf32(pv);
            }
            sum += __shfl_xor_sync(0xffffffffu, sum, 1);
            sum += __shfl_xor_sync(0xffffffffu, sum, 2);
            sum += __shfl_xor_sync(0xffffffffu, sum, 4);
            if (part == 0) lrow[r] += sum;
        }
        __syncthreads();

        // O += P @ V : warp tile 16x32 (V raw fp32)
#pragma unroll
        for (int kk = 0; kk < 8; kk++) {
            wmma::fragment<wmma::matrix_a, 16, 16, 8, wmma::precision::tf32, wmma::row_major> a;
            wmma::load_matrix_sync(a, Ss + (wm * 16) * LDS + kk * 8, LDS);
#pragma unroll
            for (int j = 0; j < 2; j++) {
                wmma::fragment<wmma::matrix_b, 16, 16, 8, wmma::precision::tf32, wmma::row_major> bv;
                wmma::load_matrix_sync(bv, Vc + (kk * 8) * LDQ + wn * 32 + j * 16, LDQ);
                wmma::mma_sync(o_acc[j], a, bv, o_acc[j]);
            }
        }
        __syncthreads();

        if (t + 2 < KVLEN / 64) load_tile(t + 2, bb);
    }

    // epilogue
    float* Os = Kb0;
#pragma unroll
    for (int j = 0; j < 2; j++)
        wmma::store_matrix_sync(Os + (wm * 16) * LDQ + wn * 32 + j * 16,
                                o_acc[j], LDQ, wmma::mem_row_major);
    __syncthreads();
    for (int i = tid; i < 64 * 32; i += 512) {
        int j = i >> 5, c = (i & 31) << 2;
        int s = j & 15, hr = j >> 4;
        float inv = 1.0f / lrow[j];
        float4 v = *reinterpret_cast<float4*>(Os + j * LDQ + c);
        v.x = to_tf32(v.x * inv); v.y = to_tf32(v.y * inv);
        v.z = to_tf32(v.z * inv); v.w = to_tf32(v.w * inv);
        *reinterpret_cast<float4*>(
            g_attn + (size_t)(b * 16 + s) * D_ + (kvh * 4 + hr) * HD_ + c) = v;
    }
}

// ---------------------------------------------------------------------------
extern "C" void kernel_launch(void* const* d_in, const int* in_sizes, int n_in,
                              void* d_out, int out_size)
{
    const float* x       = (const float*)d_in[0];
    const float* fcos    = (const float*)d_in[1];
    const float* fsin    = (const float*)d_in[2];
    const float* cache_k = (const float*)d_in[4];
    const float* cache_v = (const float*)d_in[5];
    const float* wq = (const float*)d_in[6];
    const float* bq = (const float*)d_in[7];
    const float* wk = (const float*)d_in[8];
    const float* bk = (const float*)d_in[9];
    const float* wv = (const float*)d_in[10];
    const float* bv = (const float*)d_in[11];
    const float* wo = (const float*)d_in[12];
    const float* bo = (const float*)d_in[13];
    float* out = (float*)d_out;

    float *qkvb, *attnb;
    cudaGetSymbolAddress((void**)&qkvb, g_qkv);
    cudaGetSymbolAddress((void**)&attnb, g_attn);

    cudaFuncSetAttribute(gemm_fused, cudaFuncAttributeMaxDynamicSharedMemorySize, G_SMEM);
    cudaFuncSetAttribute(attn_kernel, cudaFuncAttributeMaxDynamicSharedMemorySize, ATT_SMEM);

    // launch 1: fused QKV projection (reads raw x / wq|wk|wv)
    gemm_fused<<<dim3(NQKV / 128, T_ / 128), 512, G_SMEM>>>(
        x, wq, wk, wv, bq, bk, bv, qkvb, NQKV, D_, 1);
    // launch 2: RoPE
    rope_kernel<<<(T_ * H_ * 64 + T_ * KV_ * 64 + 255) / 256, 256>>>(fcos, fsin);
    // launch 3: attention
    attn_kernel<<<B_ * KV_, 512, ATT_SMEM>>>(cache_k, cache_v);
    // launch 4: O projection  (profiler slot)
    gemm_fused<<<dim3(D_ / 128, T_ / 128), 512, G_SMEM>>>(
        attnb, wo, wo, wo, bo, bo, bo, out, D_, D_, 0);
}

// round 7
// speedup vs baseline: 1.1501x; 1.1501x over previous
#include <cuda_runtime.h>
#include <cuda_bf16.h>
#include <mma.h>
#include <cstdint>

using namespace nvcuda;

#define B_    16
#define S_    16
#define D_    4096
#define H_    32
#define KV_   8
#define HD_   128
#define T_    256
#define KVLEN 4096
#define STARTP 4080
#define NQKV  6144

// ----------------------------- device scratch ------------------------------
__device__ float g_qkv[T_ * NQKV];
__device__ float g_attn[T_ * D_];

// ----------------------------- helpers ---------------------------------
__device__ __forceinline__ uint32_t smem_u32(const void* p) {
    uint32_t a;
    asm("{ .reg .u64 t; cvta.to.shared.u64 t, %1; cvt.u32.u64 %0, t; }" : "=r"(a) : "l"(p));
    return a;
}
__device__ __forceinline__ void cp16(uint32_t dst, const void* src) {
    asm volatile("cp.async.cg.shared.global [%0], [%1], 16;" :: "r"(dst), "l"(src));
}
__device__ __forceinline__ void cp_commit() { asm volatile("cp.async.commit_group;" ::: "memory"); }
template<int N> __device__ __forceinline__ void cp_wait() {
    asm volatile("cp.async.wait_group %0;" :: "n"(N) : "memory");
}
__device__ __forceinline__ float to_tf32(float x) { return wmma::__float_to_tf32(x); }

template<class Frag>
__device__ __forceinline__ void round_frag(Frag& f) {
#pragma unroll
    for (int i = 0; i < f.num_elements; i++) f.x[i] = to_tf32(f.x[i]);
}

// ---------------------------------------------------------------------------
// tf32 GEMM: BM=64, BN=128, BK=64, 256 threads (8 warps, 2x4 grid, 32x32
// warp tiles), 2-stage cp.async, 2 CTAs/SM. RAW fp32 operands, fragments
// RN-rounded in registers.
// ---------------------------------------------------------------------------
#define GBK 64
#define GLDA 68
#define GLDB 132
#define G_A_FLOATS (64 * GLDA)                     // 4352
#define G_STAGE_FLOATS (G_A_FLOATS + GBK * GLDB)   // 4352+8448=12800
#define G_SMEM (2 * G_STAGE_FLOATS * 4)            // 102400 B -> 2 CTAs/SM

__global__ __launch_bounds__(256, 2) void gemm_fused(
    const float* __restrict__ A,
    const float* __restrict__ w0, const float* __restrict__ w1, const float* __restrict__ w2,
    const float* __restrict__ b0, const float* __restrict__ b1, const float* __restrict__ b2,
    float* __restrict__ C, int Nt, int K, int qkv_mode)
{
    extern __shared__ __align__(16) float sm[];
    float* stage[2] = { sm, sm + G_STAGE_FLOATS };

    const int tid  = threadIdx.x;
    const int warp = tid >> 5;
    const int wm   = warp >> 2;       // 0..1 -> rows wm*32
    const int wn   = warp & 3;        // 0..3 -> cols wn*32
    const int m0 = blockIdx.y * 64;
    const int n0 = blockIdx.x * 128;
    const int NC = K / GBK;

    const float* Bsrc; const float* biasp; int bstride;
    if (qkv_mode) {
        if (n0 < 4096)      { Bsrc = w0 + n0;          biasp = b0 + n0;        bstride = 4096; }
        else if (n0 < 5120) { Bsrc = w1 + (n0 - 4096); biasp = b1 + (n0-4096); bstride = 1024; }
        else                { Bsrc = w2 + (n0 - 5120); biasp = b2 + (n0-5120); bstride = 1024; }
    } else {
        Bsrc = w0 + n0; biasp = b0 + n0; bstride = Nt;
    }

    const uint32_t sa[2] = { smem_u32(stage[0]), smem_u32(stage[1]) };

    auto load_tile = [&](int c, int b) {
        const int k0 = c * GBK;
        const uint32_t st = sa[b];
        const uint32_t stB = st + G_A_FLOATS * 4;
#pragma unroll
        for (int i = tid; i < 1024; i += 256) {          // A: 64 x 16 float4
            int r = i >> 4, c4 = (i & 15) << 2;
            cp16(st + (uint32_t)(r * GLDA + c4) * 4u, A + (size_t)(m0 + r) * K + k0 + c4);
        }
#pragma unroll
        for (int i = tid; i < 2048; i += 256) {          // B: 64 x 32 float4
            int r = i >> 5, c4 = (i & 31) << 2;
            cp16(stB + (uint32_t)(r * GLDB + c4) * 4u, Bsrc + (size_t)(k0 + r) * bstride + c4);
        }
        cp_commit();
    };

    wmma::fragment<wmma::accumulator, 16, 16, 8, float> acc[2][2];
#pragma unroll
    for (int i = 0; i < 2; i++)
#pragma unroll
        for (int j = 0; j < 2; j++) wmma::fill_fragment(acc[i][j], 0.0f);

    load_tile(0, 0);
    load_tile(1, 1);

    for (int c = 0; c < NC; c++) {
        const int b = c & 1;
        if (c + 1 < NC) cp_wait<1>(); else cp_wait<0>();
        __syncthreads();

        const float* As = stage[b];
        const float* Bs = stage[b] + G_A_FLOATS;
#pragma unroll
        for (int kk = 0; kk < GBK; kk += 8) {
            wmma::fragment<wmma::matrix_a, 16, 16, 8, wmma::precision::tf32, wmma::row_major> a[2];
            wmma::fragment<wmma::matrix_b, 16, 16, 8, wmma::precision::tf32, wmma::row_major> bf[2];
#pragma unroll
            for (int i = 0; i < 2; i++) {
                wmma::load_matrix_sync(a[i], As + (wm * 32 + i * 16) * GLDA + kk, GLDA);
                round_frag(a[i]);
            }
#pragma unroll
            for (int j = 0; j < 2; j++) {
                wmma::load_matrix_sync(bf[j], Bs + kk * GLDB + wn * 32 + j * 16, GLDB);
                round_frag(bf[j]);
            }
#pragma unroll
            for (int i = 0; i < 2; i++)
#pragma unroll
                for (int j = 0; j < 2; j++)
                    wmma::mma_sync(acc[i][j], a[i], bf[j], acc[i][j]);
        }
        __syncthreads();
        if (c + 2 < NC) load_tile(c + 2, b);
    }

    // epilogue: frags -> smem [64][132] -> +bias -> gmem
    float* Cs = sm;
#pragma unroll
    for (int i = 0; i < 2; i++)
#pragma unroll
        for (int j = 0; j < 2; j++)
            wmma::store_matrix_sync(Cs + (wm * 32 + i * 16) * GLDB + wn * 32 + j * 16,
                                    acc[i][j], GLDB, wmma::mem_row_major);
    __syncthreads();
    for (int i = tid; i < 64 * 32; i += 256) {
        int r = i >> 5, c4 = (i & 31) << 2;
        float4 v = *reinterpret_cast<float4*>(Cs + r * GLDB + c4);
        float4 bb = *reinterpret_cast<const float4*>(biasp + c4);
        v.x += bb.x; v.y += bb.y; v.z += bb.z; v.w += bb.w;
        *reinterpret_cast<float4*>(C + (size_t)(m0 + r) * Nt + n0 + c4) = v;
    }
}

// ---------------------------------------------------------------------------
// RoPE in place on g_qkv
// ---------------------------------------------------------------------------
__global__ void rope_kernel(const float* __restrict__ fc, const float* __restrict__ fs)
{
    const int QP = T_ * H_ * 64;
    const int KP = T_ * KV_ * 64;
    int idx = blockIdx.x * blockDim.x + threadIdx.x;
    if (idx < QP) {
        int c = idx & 63, h = (idx >> 6) & 31, m = idx >> 11;
        int s = m & 15;
        float co = fc[s * 64 + c], sn = fs[s * 64 + c];
        float* p = g_qkv + (size_t)m * NQKV + h * 128 + 2 * c;
        float x0 = p[0], x1 = p[1];
        p[0] = x0 * co - x1 * sn;
        p[1] = x0 * sn + x1 * co;
    } else if (idx < QP + KP) {
        int j = idx - QP;
        int c = j & 63, kvh = (j >> 6) & 7, m = j >> 9;
        int s = m & 15;
        float co = fc[s * 64 + c], sn = fs[s * 64 + c];
        float* p = g_qkv + (size_t)m * NQKV + 4096 + kvh * 128 + 2 * c;
        float x0 = p[0], x1 = p[1];
        p[0] = x0 * co - x1 * sn;
        p[1] = x0 * sn + x1 * co;
    }
}

// ---------------------------------------------------------------------------
// attention: 512 threads / 16 warps, K rounded in-fragment, cp.async
// double-buffered tiles (unchanged from R6).
// ---------------------------------------------------------------------------
#define LDQ 132
#define LDS 68
#define ATT_SMEM ((64 * LDQ * 5 + 64 * LDS + 64) * 4)

__global__ __launch_bounds__(512) void attn_kernel(
    const float* __restrict__ cache_k, const float* __restrict__ cache_v)
{
    extern __shared__ __align__(16) float smem[];
    float* Qs   = smem;
    float* Kb0  = Qs + 64 * LDQ;
    float* Kb1  = Kb0 + 64 * LDQ;
    float* Vb0  = Kb1 + 64 * LDQ;
    float* Vb1  = Vb0 + 64 * LDQ;
    float* Ss   = Vb1 + 64 * LDQ;
    float* lrow = Ss + 64 * LDS;

    const int b   = blockIdx.x >> 3;
    const int kvh = blockIdx.x & 7;
    const int tid = threadIdx.x;
    const int warp = tid >> 5;
    const int wm = warp >> 2;
    const int wn = warp & 3;

    const uint32_t kaddr[2] = { smem_u32(Kb0), smem_u32(Kb1) };
    const uint32_t vaddr[2] = { smem_u32(Vb0), smem_u32(Vb1) };

    auto load_tile = [&](int t, int bb) {
        const int p0 = t * 64;
        const uint32_t ka = kaddr[bb], va = vaddr[bb];
#pragma unroll
        for (int i = tid; i < 2048; i += 512) {
            int r = i >> 5, c16 = i & 31;
            int p = p0 + r;
            const float *srck, *srcv;
            if (p < STARTP) {
                size_t o = (((size_t)b * KVLEN + p) * KV_ + kvh) * (size_t)HD_ + c16 * 4;
                srck = cache_k + o; srcv = cache_v + o;
            } else {
                size_t row = (size_t)(b * 16 + p - STARTP) * NQKV;
                srck = g_qkv + row + 4096 + kvh * 128 + c16 * 4;
                srcv = g_qkv + row + 5120 + kvh * 128 + c16 * 4;
            }
            uint32_t doff = (uint32_t)(r * LDQ + c16 * 4) * 4u;
            cp16(ka + doff, srck);
            cp16(va + doff, srcv);
        }
        cp_commit();
    };

    load_tile(0, 0);
    load_tile(1, 1);

    const float scale = 0.08838834764831845f;
    for (int i = tid; i < 64 * 32; i += 512) {
        int j = i >> 5, c = (i & 31) << 2;
        int s = j & 15, hr = j >> 4;
        float4 v = *reinterpret_cast<const float4*>(
            g_qkv + (size_t)(b * 16 + s) * NQKV + (kvh * 4 + hr) * HD_ + c);
        float* d = Qs + j * LDQ + c;
        d[0] = to_tf32(v.x * scale); d[1] = to_tf32(v.y * scale);
        d[2] = to_tf32(v.z * scale); d[3] = to_tf32(v.w * scale);
    }
    if (tid < 64) lrow[tid] = 0.0f;
    __syncthreads();

    wmma::fragment<wmma::matrix_a, 16, 16, 8, wmma::precision::tf32, wmma::row_major> qf[16];
#pragma unroll
    for (int kk = 0; kk < 16; kk++)
        wmma::load_matrix_sync(qf[kk], Qs + (wm * 16) * LDQ + kk * 8, LDQ);

    wmma::fragment<wmma::accumulator, 16, 16, 8, float> o_acc[2];
#pragma unroll
    for (int j = 0; j < 2; j++) wmma::fill_fragment(o_acc[j], 0.0f);

    for (int t = 0; t < KVLEN / 64; t++) {
        const int bb = t & 1;
        float* Kc = bb ? Kb1 : Kb0;
        float* Vc = bb ? Vb1 : Vb0;
        const int p0 = t * 64;

        if (t + 1 < KVLEN / 64) cp_wait<1>(); else cp_wait<0>();
        __syncthreads();

        {
            wmma::fragment<wmma::accumulator, 16, 16, 8, float> s_acc;
            wmma::fill_fragment(s_acc, 0.0f);
#pragma unroll
            for (int kk = 0; kk < 16; kk++) {
                wmma::fragment<wmma::matrix_b, 16, 16, 8, wmma::precision::tf32, wmma::col_major> bk;
                wmma::load_matrix_sync(bk, Kc + (wn * 16) * LDQ + kk * 8, LDQ);
                round_frag(bk);
                wmma::mma_sync(s_acc, qf[kk], bk, s_acc);
            }
            wmma::store_matrix_sync(Ss + (wm * 16) * LDS + wn * 16, s_acc, LDS,
                                    wmma::mem_row_major);
        }
        __syncthreads();

        {
            int r = tid >> 3, part = tid & 7;
            int lim = STARTP + (r & 15);
            float* row = Ss + r * LDS + part * 8;
            int pbase = p0 + part * 8;
            float sum = 0.0f;
#pragma unroll
            for (int c = 0; c < 8; c++) {
                float v = row[c];
                float pv = (pbase + c <= lim) ? __expf(v) : 0.0f;
                sum += pv;
                row[c] = to_tf32(pv);
            }
            sum += __shfl_xor_sync(0xffffffffu, sum, 1);
            sum += __shfl_xor_sync(0xffffffffu, sum, 2);
            sum += __shfl_xor_sync(0xffffffffu, sum, 4);
            if (part == 0) lrow[r] += sum;
        }
        __syncthreads();

#pragma unroll
        for (int kk = 0; kk < 8; kk++) {
            wmma::fragment<wmma::matrix_a, 16, 16, 8, wmma::precision::tf32, wmma::row_major> a;
            wmma::load_matrix_sync(a, Ss + (wm * 16) * LDS + kk * 8, LDS);
#pragma unroll
            for (int j = 0; j < 2; j++) {
                wmma::fragment<wmma::matrix_b, 16, 16, 8, wmma::precision::tf32, wmma::row_major> bv;
                wmma::load_matrix_sync(bv, Vc + (kk * 8) * LDQ + wn * 32 + j * 16, LDQ);
                wmma::mma_sync(o_acc[j], a, bv, o_acc[j]);
            }
        }
        __syncthreads();

        if (t + 2 < KVLEN / 64) load_tile(t + 2, bb);
    }

    float* Os = Kb0;
#pragma unroll
    for (int j = 0; j < 2; j++)
        wmma::store_matrix_sync(Os + (wm * 16) * LDQ + wn * 32 + j * 16,
                                o_acc[j], LDQ, wmma::mem_row_major);
    __syncthreads();
    for (int i = tid; i < 64 * 32; i += 512) {
        int j = i >> 5, c = (i & 31) << 2;
        int s = j & 15, hr = j >> 4;
        float inv = 1.0f / lrow[j];
        float4 v = *reinterpret_cast<float4*>(Os + j * LDQ + c);
        v.x = to_tf32(v.x * inv); v.y = to_tf32(v.y * inv);
        v.z = to_tf32(v.z * inv); v.w = to_tf32(v.w * inv);
        *reinterpret_cast<float4*>(
            g_attn + (size_t)(b * 16 + s) * D_ + (kvh * 4 + hr) * HD_ + c) = v;
    }
}

// ---------------------------------------------------------------------------
extern "C" void kernel_launch(void* const* d_in, const int* in_sizes, int n_in,
                              void* d_out, int out_size)
{
    const float* x       = (const float*)d_in[0];
    const float* fcos    = (const float*)d_in[1];
    const float* fsin    = (const float*)d_in[2];
    const float* cache_k = (const float*)d_in[4];
    const float* cache_v = (const float*)d_in[5];
    const float* wq = (const float*)d_in[6];
    const float* bq = (const float*)d_in[7];
    const float* wk = (const float*)d_in[8];
    const float* bk = (const float*)d_in[9];
    const float* wv = (const float*)d_in[10];
    const float* bv = (const float*)d_in[11];
    const float* wo = (const float*)d_in[12];
    const float* bo = (const float*)d_in[13];
    float* out = (float*)d_out;

    float *qkvb, *attnb;
    cudaGetSymbolAddress((void**)&qkvb, g_qkv);
    cudaGetSymbolAddress((void**)&attnb, g_attn);

    cudaFuncSetAttribute(gemm_fused, cudaFuncAttributeMaxDynamicSharedMemorySize, G_SMEM);
    cudaFuncSetAttribute(attn_kernel, cudaFuncAttributeMaxDynamicSharedMemorySize, ATT_SMEM);

    // launch 1: fused QKV projection (192 CTAs)
    gemm_fused<<<dim3(NQKV / 128, T_ / 64), 256, G_SMEM>>>(
        x, wq, wk, wv, bq, bk, bv, qkvb, NQKV, D_, 1);
    // launch 2: RoPE
    rope_kernel<<<(T_ * H_ * 64 + T_ * KV_ * 64 + 255) / 256, 256>>>(fcos, fsin);
    // launch 3: attention
    attn_kernel<<<B_ * KV_, 512, ATT_SMEM>>>(cache_k, cache_v);
    // launch 4: O projection (128 CTAs)  (profiler slot)
    gemm_fused<<<dim3(D_ / 128, T_ / 64), 256, G_SMEM>>>(
        attnb, wo, wo, wo, bo, bo, bo, out, D_, D_, 0);
}

// round 8
// speedup vs baseline: 1.2698x; 1.1041x over previous
#include <cuda_runtime.h>
#include <cuda_bf16.h>
#include <mma.h>
#include <cstdint>

using namespace nvcuda;

#define B_    16
#define S_    16
#define D_    4096
#define H_    32
#define KV_   8
#define HD_   128
#define T_    256
#define KVLEN 4096
#define STARTP 4080
#define NQKV  6144

// ----------------------------- device scratch ------------------------------
__device__ float g_qkv[T_ * NQKV];
__device__ float g_attn[T_ * D_];
__device__ float g_part[2 * T_ * NQKV];    // split-K partials (covers QKV and O)

// ----------------------------- helpers ---------------------------------
__device__ __forceinline__ uint32_t smem_u32(const void* p) {
    uint32_t a;
    asm("{ .reg .u64 t; cvta.to.shared.u64 t, %1; cvt.u32.u64 %0, t; }" : "=r"(a) : "l"(p));
    return a;
}
__device__ __forceinline__ void cp16(uint32_t dst, const void* src) {
    asm volatile("cp.async.cg.shared.global [%0], [%1], 16;" :: "r"(dst), "l"(src));
}
__device__ __forceinline__ void cp_commit() { asm volatile("cp.async.commit_group;" ::: "memory"); }
template<int N> __device__ __forceinline__ void cp_wait() {
    asm volatile("cp.async.wait_group %0;" :: "n"(N) : "memory");
}
__device__ __forceinline__ float to_tf32(float x) { return wmma::__float_to_tf32(x); }

template<class Frag>
__device__ __forceinline__ void round_frag(Frag& f) {
#pragma unroll
    for (int i = 0; i < f.num_elements; i++) f.x[i] = to_tf32(f.x[i]);
}

// ---------------------------------------------------------------------------
// tf32 GEMM, split-K=2 (blockIdx.z): BM=64, BN=128, BK=64, 256 threads,
// 2-stage cp.async, 2 CTAs/SM. Writes fp32 partials (no bias).
// ---------------------------------------------------------------------------
#define GBK 64
#define GLDA 68
#define GLDB 132
#define G_A_FLOATS (64 * GLDA)                     // 4352
#define G_STAGE_FLOATS (G_A_FLOATS + GBK * GLDB)   // 12800
#define G_SMEM (2 * G_STAGE_FLOATS * 4)            // 102400 B

__global__ __launch_bounds__(256, 2) void gemm_splitk(
    const float* __restrict__ A,
    const float* __restrict__ w0, const float* __restrict__ w1, const float* __restrict__ w2,
    float* __restrict__ Cpart, int Nt, int K, int qkv_mode)
{
    extern __shared__ __align__(16) float sm[];
    float* stage[2] = { sm, sm + G_STAGE_FLOATS };

    const int tid  = threadIdx.x;
    const int warp = tid >> 5;
    const int wm   = warp >> 2;       // 0..1 -> rows wm*32
    const int wn   = warp & 3;        // 0..3 -> cols wn*32
    const int m0 = blockIdx.y * 64;
    const int n0 = blockIdx.x * 128;
    const int kb = blockIdx.z * (K / 2);           // K-range start
    const int NC = (K / 2) / GBK;                  // 32 chunks

    float* Cp = Cpart + (size_t)blockIdx.z * T_ * Nt;

    const float* Bsrc; int bstride;
    if (qkv_mode) {
        if (n0 < 4096)      { Bsrc = w0 + n0;          bstride = 4096; }
        else if (n0 < 5120) { Bsrc = w1 + (n0 - 4096); bstride = 1024; }
        else                { Bsrc = w2 + (n0 - 5120); bstride = 1024; }
    } else {
        Bsrc = w0 + n0; bstride = Nt;
    }

    const uint32_t sa[2] = { smem_u32(stage[0]), smem_u32(stage[1]) };

    auto load_tile = [&](int c, int b) {
        const int k0 = kb + c * GBK;
        const uint32_t st = sa[b];
        const uint32_t stB = st + G_A_FLOATS * 4;
#pragma unroll
        for (int i = tid; i < 1024; i += 256) {          // A: 64 x 16 float4
            int r = i >> 4, c4 = (i & 15) << 2;
            cp16(st + (uint32_t)(r * GLDA + c4) * 4u, A + (size_t)(m0 + r) * K + k0 + c4);
        }
#pragma unroll
        for (int i = tid; i < 2048; i += 256) {          // B: 64 x 32 float4
            int r = i >> 5, c4 = (i & 31) << 2;
            cp16(stB + (uint32_t)(r * GLDB + c4) * 4u, Bsrc + (size_t)(k0 + r) * bstride + c4);
        }
        cp_commit();
    };

    wmma::fragment<wmma::accumulator, 16, 16, 8, float> acc[2][2];
#pragma unroll
    for (int i = 0; i < 2; i++)
#pragma unroll
        for (int j = 0; j < 2; j++) wmma::fill_fragment(acc[i][j], 0.0f);

    load_tile(0, 0);
    load_tile(1, 1);

    for (int c = 0; c < NC; c++) {
        const int b = c & 1;
        if (c + 1 < NC) cp_wait<1>(); else cp_wait<0>();
        __syncthreads();

        const float* As = stage[b];
        const float* Bs = stage[b] + G_A_FLOATS;
#pragma unroll
        for (int kk = 0; kk < GBK; kk += 8) {
            wmma::fragment<wmma::matrix_a, 16, 16, 8, wmma::precision::tf32, wmma::row_major> a[2];
            wmma::fragment<wmma::matrix_b, 16, 16, 8, wmma::precision::tf32, wmma::row_major> bf[2];
#pragma unroll
            for (int i = 0; i < 2; i++) {
                wmma::load_matrix_sync(a[i], As + (wm * 32 + i * 16) * GLDA + kk, GLDA);
                round_frag(a[i]);
            }
#pragma unroll
            for (int j = 0; j < 2; j++) {
                wmma::load_matrix_sync(bf[j], Bs + kk * GLDB + wn * 32 + j * 16, GLDB);
                round_frag(bf[j]);
            }
#pragma unroll
            for (int i = 0; i < 2; i++)
#pragma unroll
                for (int j = 0; j < 2; j++)
                    wmma::mma_sync(acc[i][j], a[i], bf[j], acc[i][j]);
        }
        __syncthreads();
        if (c + 2 < NC) load_tile(c + 2, b);
    }

    // epilogue: frags -> smem -> gmem partial (no bias)
    float* Cs = sm;
#pragma unroll
    for (int i = 0; i < 2; i++)
#pragma unroll
        for (int j = 0; j < 2; j++)
            wmma::store_matrix_sync(Cs + (wm * 32 + i * 16) * GLDB + wn * 32 + j * 16,
                                    acc[i][j], GLDB, wmma::mem_row_major);
    __syncthreads();
    for (int i = tid; i < 64 * 32; i += 256) {
        int r = i >> 5, c4 = (i & 31) << 2;
        float4 v = *reinterpret_cast<float4*>(Cs + r * GLDB + c4);
        *reinterpret_cast<float4*>(Cp + (size_t)(m0 + r) * Nt + n0 + c4) = v;
    }
}

// ---------------------------------------------------------------------------
// qkv_finish: g_qkv = part0 + part1 + bias, with RoPE fused for q/k regions.
// ---------------------------------------------------------------------------
__global__ void qkv_finish(const float* __restrict__ bq, const float* __restrict__ bk,
                           const float* __restrict__ bv,
                           const float* __restrict__ fc, const float* __restrict__ fs)
{
    const int N4 = NQKV / 4;
    int i = blockIdx.x * blockDim.x + threadIdx.x;
    if (i >= T_ * N4) return;
    int m = i / N4, n4 = (i % N4) * 4;
    size_t idx = (size_t)m * NQKV + n4;

    const float* p0 = g_part + idx;
    const float* p1 = g_part + (size_t)T_ * NQKV + idx;
    float4 a = *reinterpret_cast<const float4*>(p0);
    float4 b = *reinterpret_cast<const float4*>(p1);
    float4 bb;
    if (n4 < 4096)      bb = *reinterpret_cast<const float4*>(bq + n4);
    else if (n4 < 5120) bb = *reinterpret_cast<const float4*>(bk + n4 - 4096);
    else                bb = *reinterpret_cast<const float4*>(bv + n4 - 5120);
    float4 v;
    v.x = a.x + b.x + bb.x; v.y = a.y + b.y + bb.y;
    v.z = a.z + b.z + bb.z; v.w = a.w + b.w + bb.w;

    if (n4 < 5120) {  // rope on q and k regions
        int s = m & 15;
        int c0 = (n4 & 127) >> 1;          // pair index within head (even)
        float co0 = fc[s * 64 + c0],     sn0 = fs[s * 64 + c0];
        float co1 = fc[s * 64 + c0 + 1], sn1 = fs[s * 64 + c0 + 1];
        float rx = v.x * co0 - v.y * sn0;
        float ry = v.x * sn0 + v.y * co0;
        float rz = v.z * co1 - v.w * sn1;
        float rw = v.z * sn1 + v.w * co1;
        v.x = rx; v.y = ry; v.z = rz; v.w = rw;
    }
    *reinterpret_cast<float4*>(g_qkv + idx) = v;
}

// ---------------------------------------------------------------------------
// o_finish: out = part0 + part1 + bias
// ---------------------------------------------------------------------------
__global__ void o_finish(const float* __restrict__ bo, float* __restrict__ out)
{
    int i = blockIdx.x * blockDim.x + threadIdx.x;
    if (i >= T_ * D_ / 4) return;
    int n4 = (i % (D_ / 4)) * 4;
    size_t idx = (size_t)i * 4;
    float4 a = *reinterpret_cast<const float4*>(g_part + idx);
    float4 b = *reinterpret_cast<const float4*>(g_part + (size_t)T_ * D_ + idx);
    float4 bb = *reinterpret_cast<const float4*>(bo + n4);
    float4 v;
    v.x = a.x + b.x + bb.x; v.y = a.y + b.y + bb.y;
    v.z = a.z + b.z + bb.z; v.w = a.w + b.w + bb.w;
    *reinterpret_cast<float4*>(out + idx) = v;
}

// ---------------------------------------------------------------------------
// attention: unchanged from R7 (control).
// ---------------------------------------------------------------------------
#define LDQ 132
#define LDS 68
#define ATT_SMEM ((64 * LDQ * 5 + 64 * LDS + 64) * 4)

__global__ __launch_bounds__(512) void attn_kernel(
    const float* __restrict__ cache_k, const float* __restrict__ cache_v)
{
    extern __shared__ __align__(16) float smem[];
    float* Qs   = smem;
    float* Kb0  = Qs + 64 * LDQ;
    float* Kb1  = Kb0 + 64 * LDQ;
    float* Vb0  = Kb1 + 64 * LDQ;
    float* Vb1  = Vb0 + 64 * LDQ;
    float* Ss   = Vb1 + 64 * LDQ;
    float* lrow = Ss + 64 * LDS;

    const int b   = blockIdx.x >> 3;
    const int kvh = blockIdx.x & 7;
    const int tid = threadIdx.x;
    const int warp = tid >> 5;
    const int wm = warp >> 2;
    const int wn = warp & 3;

    const uint32_t kaddr[2] = { smem_u32(Kb0), smem_u32(Kb1) };
    const uint32_t vaddr[2] = { smem_u32(Vb0), smem_u32(Vb1) };

    auto load_tile = [&](int t, int bb) {
        const int p0 = t * 64;
        const uint32_t ka = kaddr[bb], va = vaddr[bb];
#pragma unroll
        for (int i = tid; i < 2048; i += 512) {
            int r = i >> 5, c16 = i & 31;
            int p = p0 + r;
            const float *srck, *srcv;
            if (p < STARTP) {
                size_t o = (((size_t)b * KVLEN + p) * KV_ + kvh) * (size_t)HD_ + c16 * 4;
                srck = cache_k + o; srcv = cache_v + o;
            } else {
                size_t row = (size_t)(b * 16 + p - STARTP) * NQKV;
                srck = g_qkv + row + 4096 + kvh * 128 + c16 * 4;
                srcv = g_qkv + row + 5120 + kvh * 128 + c16 * 4;
            }
            uint32_t doff = (uint32_t)(r * LDQ + c16 * 4) * 4u;
            cp16(ka + doff, srck);
            cp16(va + doff, srcv);
        }
        cp_commit();
    };

    load_tile(0, 0);
    load_tile(1, 1);

    const float scale = 0.08838834764831845f;
    for (int i = tid; i < 64 * 32; i += 512) {
        int j = i >> 5, c = (i & 31) << 2;
        int s = j & 15, hr = j >> 4;
        float4 v = *reinterpret_cast<const float4*>(
            g_qkv + (size_t)(b * 16 + s) * NQKV + (kvh * 4 + hr) * HD_ + c);
        float* d = Qs + j * LDQ + c;
        d[0] = to_tf32(v.x * scale); d[1] = to_tf32(v.y * scale);
        d[2] = to_tf32(v.z * scale); d[3] = to_tf32(v.w * scale);
    }
    if (tid < 64) lrow[tid] = 0.0f;
    __syncthreads();

    wmma::fragment<wmma::matrix_a, 16, 16, 8, wmma::precision::tf32, wmma::row_major> qf[16];
#pragma unroll
    for (int kk = 0; kk < 16; kk++)
        wmma::load_matrix_sync(qf[kk], Qs + (wm * 16) * LDQ + kk * 8, LDQ);

    wmma::fragment<wmma::accumulator, 16, 16, 8, float> o_acc[2];
#pragma unroll
    for (int j = 0; j < 2; j++) wmma::fill_fragment(o_acc[j], 0.0f);

    for (int t = 0; t < KVLEN / 64; t++) {
        const int bb = t & 1;
        float* Kc = bb ? Kb1 : Kb0;
        float* Vc = bb ? Vb1 : Vb0;
        const int p0 = t * 64;

        if (t + 1 < KVLEN / 64) cp_wait<1>(); else cp_wait<0>();
        __syncthreads();

        {
            wmma::fragment<wmma::accumulator, 16, 16, 8, float> s_acc;
            wmma::fill_fragment(s_acc, 0.0f);
#pragma unroll
            for (int kk = 0; kk < 16; kk++) {
                wmma::fragment<wmma::matrix_b, 16, 16, 8, wmma::precision::tf32, wmma::col_major> bk;
                wmma::load_matrix_sync(bk, Kc + (wn * 16) * LDQ + kk * 8, LDQ);
                round_frag(bk);
                wmma::mma_sync(s_acc, qf[kk], bk, s_acc);
            }
            wmma::store_matrix_sync(Ss + (wm * 16) * LDS + wn * 16, s_acc, LDS,
                                    wmma::mem_row_major);
        }
        __syncthreads();

        {
            int r = tid >> 3, part = tid & 7;
            int lim = STARTP + (r & 15);
            float* row = Ss + r * LDS + part * 8;
            int pbase = p0 + part * 8;
            float sum = 0.0f;
#pragma unroll
            for (int c = 0; c < 8; c++) {
                float v = row[c];
                float pv = (pbase + c <= lim) ? __expf(v) : 0.0f;
                sum += pv;
                row[c] = to_tf32(pv);
            }
            sum += __shfl_xor_sync(0xffffffffu, sum, 1);
            sum += __shfl_xor_sync(0xffffffffu, sum, 2);
            sum += __shfl_xor_sync(0xffffffffu, sum, 4);
            if (part == 0) lrow[r] += sum;
        }
        __syncthreads();

#pragma unroll
        for (int kk = 0; kk < 8; kk++) {
            wmma::fragment<wmma::matrix_a, 16, 16, 8, wmma::precision::tf32, wmma::row_major> a;
            wmma::load_matrix_sync(a, Ss + (wm * 16) * LDS + kk * 8, LDS);
#pragma unroll
            for (int j = 0; j < 2; j++) {
                wmma::fragment<wmma::matrix_b, 16, 16, 8, wmma::precision::tf32, wmma::row_major> bv;
                wmma::load_matrix_sync(bv, Vc + (kk * 8) * LDQ + wn * 32 + j * 16, LDQ);
                wmma::mma_sync(o_acc[j], a, bv, o_acc[j]);
            }
        }
        __syncthreads();

        if (t + 2 < KVLEN / 64) load_tile(t + 2, bb);
    }

    float* Os = Kb0;
#pragma unroll
    for (int j = 0; j < 2; j++)
        wmma::store_matrix_sync(Os + (wm * 16) * LDQ + wn * 32 + j * 16,
                                o_acc[j], LDQ, wmma::mem_row_major);
    __syncthreads();
    for (int i = tid; i < 64 * 32; i += 512) {
        int j = i >> 5, c = (i & 31) << 2;
        int s = j & 15, hr = j >> 4;
        float inv = 1.0f / lrow[j];
        float4 v = *reinterpret_cast<float4*>(Os + j * LDQ + c);
        v.x = to_tf32(v.x * inv); v.y = to_tf32(v.y * inv);
        v.z = to_tf32(v.z * inv); v.w = to_tf32(v.w * inv);
        *reinterpret_cast<float4*>(
            g_attn + (size_t)(b * 16 + s) * D_ + (kvh * 4 + hr) * HD_ + c) = v;
    }
}

// ---------------------------------------------------------------------------
extern "C" void kernel_launch(void* const* d_in, const int* in_sizes, int n_in,
                              void* d_out, int out_size)
{
    const float* x       = (const float*)d_in[0];
    const float* fcos    = (const float*)d_in[1];
    const float* fsin    = (const float*)d_in[2];
    const float* cache_k = (const float*)d_in[4];
    const float* cache_v = (const float*)d_in[5];
    const float* wq = (const float*)d_in[6];
    const float* bq = (const float*)d_in[7];
    const float* wk = (const float*)d_in[8];
    const float* bk = (const float*)d_in[9];
    const float* wv = (const float*)d_in[10];
    const float* bv = (const float*)d_in[11];
    const float* wo = (const float*)d_in[12];
    const float* bo = (const float*)d_in[13];
    float* out = (float*)d_out;

    float *attnb;
    cudaGetSymbolAddress((void**)&attnb, g_attn);
    float *partb;
    cudaGetSymbolAddress((void**)&partb, g_part);

    cudaFuncSetAttribute(gemm_splitk, cudaFuncAttributeMaxDynamicSharedMemorySize, G_SMEM);
    cudaFuncSetAttribute(attn_kernel, cudaFuncAttributeMaxDynamicSharedMemorySize, ATT_SMEM);

    // 1: fused QKV projection, split-K=2 (384 CTAs)
    gemm_splitk<<<dim3(NQKV / 128, T_ / 64, 2), 256, G_SMEM>>>(
        x, wq, wk, wv, partb, NQKV, D_, 1);
    // 2: reduce partials + bias + RoPE
    qkv_finish<<<(T_ * (NQKV / 4) + 255) / 256, 256>>>(bq, bk, bv, fcos, fsin);
    // 3: attention
    attn_kernel<<<B_ * KV_, 512, ATT_SMEM>>>(cache_k, cache_v);
    // 4: O projection, split-K=2 (256 CTAs)
    gemm_splitk<<<dim3(D_ / 128, T_ / 64, 2), 256, G_SMEM>>>(
        attnb, wo, wo, wo, partb, D_, D_, 0);
    // 5: reduce partials + bias -> out
    o_finish<<<(T_ * (D_ / 4) + 255) / 256, 256>>>(bo, out);
}